// round 4
// baseline (speedup 1.0000x reference)
#include <cuda_runtime.h>

// Blur: depthwise 4x4 FIR (separable [1,3,3,1] ⊗ [1,3,3,1] / 16), pad (1,1).
// Input (4,128,513,513) f32 -> Output (4,128,512,512) f32.
//
// Round-4: R2 structure (LDG x5 -> STS x5 staged rows, compiler-scheduled MLP,
// unroll 4, warp-private double buffer) + R3's predicated boundary loads
// (fewer regs) + occupancy bound raised to 12 CTAs/SM.
// Horizontal FIR from two aligned LDS.128/thread (4 cols/thread); vertical
// FIR in a 4-entry register ring; one STG.128/thread/row.

#define W_IN   513
#define H_IN   513
#define W_OUT  512
#define H_OUT  512
#define STRIP  64
#define BUFSZ  160      // 132 used; padded headroom
#define NPLANE 512      // 4*128

__global__ __launch_bounds__(128, 12)
void blur_smem2_kernel(const float* __restrict__ in, float* __restrict__ out)
{
    __shared__ float sbuf[4][2][BUFSZ];   // [warp][double-buffer][idx]

    const int tid   = threadIdx.x;
    const int warp  = tid >> 5;
    const int lane  = tid & 31;
    const int plane = blockIdx.y;
    const int y0    = blockIdx.x * STRIP;
    const int wx0   = warp << 7;          // warp's first output col

    const float* ip = in  + (size_t)plane * (W_IN  * H_IN);
    float*       op = out + (size_t)plane * (W_OUT * H_OUT);

    // Window: buf[i] = in[row][wx0 - 1 + i], i in [0,131). Lane handles
    // idx = lane + 32k, k=0..4. Only k=0 (left edge: warp0 lane0) and k=4
    // (idx>=131 or right edge) can be out of range -> predicated loads.
    const int  goff = wx0 - 1 + lane;                 // col for k=0
    const bool m0   = (goff >= 0);
    const bool m4   = (lane < 3) && (goff + 128 < W_IN);

    float* __restrict__ buf0 = &sbuf[warp][0][0];
    float* __restrict__ buf1 = &sbuf[warp][1][0];

    // Stage one input row into buf (pad rows -> zeros, warp-uniform branch).
    auto stage = [&](int r, float* __restrict__ buf) {
        if ((unsigned)r < (unsigned)H_IN) {
            const float* __restrict__ rp = ip + (size_t)r * W_IN + goff;
            float v0 = m0 ? __ldg(rp)       : 0.0f;
            float v1 = __ldg(rp + 32);
            float v2 = __ldg(rp + 64);
            float v3 = __ldg(rp + 96);
            float v4 = m4 ? __ldg(rp + 128) : 0.0f;
            buf[lane      ] = v0;
            buf[lane +  32] = v1;
            buf[lane +  64] = v2;
            buf[lane +  96] = v3;
            buf[lane + 128] = v4;
        } else {
            buf[lane      ] = 0.0f;
            buf[lane +  32] = 0.0f;
            buf[lane +  64] = 0.0f;
            buf[lane +  96] = 0.0f;
            buf[lane + 128] = 0.0f;
        }
    };

    // Horizontal FIR: window buf[4l .. 4l+6] = in[x0-1 .. x0+5], x0 = wx0+4l.
    auto hcalc = [&](const float* __restrict__ buf) -> float4 {
        float4 a = *reinterpret_cast<const float4*>(buf + 4 * lane);       // x0-1..x0+2
        float4 c = *reinterpret_cast<const float4*>(buf + 4 * lane + 4);   // x0+3..x0+6
        float4 h;
        h.x = a.x + 3.0f * (a.y + a.z) + a.w;
        h.y = a.y + 3.0f * (a.z + a.w) + c.x;
        h.z = a.z + 3.0f * (a.w + c.x) + c.y;
        h.w = a.w + 3.0f * (c.x + c.y) + c.z;
        return h;
    };

    float4 h[4];
    stage(y0 - 1, buf0); __syncwarp(); h[0] = hcalc(buf0);
    stage(y0,     buf1); __syncwarp(); h[1] = hcalc(buf1);
    stage(y0 + 1, buf0); __syncwarp(); h[2] = hcalc(buf0);

    #pragma unroll 4
    for (int i = 0; i < STRIP; ++i) {
        float* __restrict__ buf = (i & 1) ? buf0 : buf1;
        stage(y0 + 2 + i, buf);
        __syncwarp();
        float4 hd = hcalc(buf);
        h[(i + 3) & 3] = hd;
        float4 ha = h[ i      & 3];
        float4 hb = h[(i + 1) & 3];
        float4 hc = h[(i + 2) & 3];

        float4 o;
        o.x = (ha.x + hd.x + 3.0f * (hb.x + hc.x)) * 0.0625f;
        o.y = (ha.y + hd.y + 3.0f * (hb.y + hc.y)) * 0.0625f;
        o.z = (ha.z + hd.z + 3.0f * (hb.z + hc.z)) * 0.0625f;
        o.w = (ha.w + hd.w + 3.0f * (hb.w + hc.w)) * 0.0625f;

        *reinterpret_cast<float4*>(op + (size_t)(y0 + i) * W_OUT + wx0 + 4 * lane) = o;
    }
}

extern "C" void kernel_launch(void* const* d_in, const int* in_sizes, int n_in,
                              void* d_out, int out_size)
{
    const float* in  = (const float*)d_in[0];
    float*       out = (float*)d_out;
    // d_in[1] is the 4x4 FIR buffer: fixed normalized [1,3,3,1] outer product
    // * factor^2 == ([1,3,3,1] ⊗ [1,3,3,1]) / 16, folded into the constants.

    dim3 grid(H_OUT / STRIP, NPLANE);   // (8, 512)
    blur_smem2_kernel<<<grid, 128>>>(in, out);
}